// round 3
// baseline (speedup 1.0000x reference)
#include <cuda_runtime.h>
#include <float.h>

// RoIPool (N=2,C=256,H=50,W=50) fp32, rois (K=256,5) -> out (K,256,7,7).
//
// R2 was issue/ALU-bound with warp divergence in the max-window loop.
// Plan: (1) transpose features to NHWC scratch; (2) lane=channel kernel:
// all lanes of a warp share one bin window (uniform bounds, zero divergence),
// loads are coalesced 128B from the L2-resident NHWC tensor. Output staged in
// smem, flushed coalesced.

#define POOLED 7
#define SCALE_F 0.0625f
#define NBINS 49
#define CH 256
#define FH 50
#define FW 50
#define HW (FH * FW)          // 2500
#define NB 2

__device__ float g_ft[NB * HW * CH];   // NHWC scratch, 5.12 MB

// ---- kernel 1: NCHW -> NHWC tiled transpose (per batch: [C=256, HW=2500] -> [HW, C])
__global__ void __launch_bounds__(1024) transpose_kernel(const float* __restrict__ in)
{
    __shared__ float tile[32][33];
    const int n   = blockIdx.z;
    const int hw0 = blockIdx.x * 32;
    const int c0  = blockIdx.y * 32;

    int tx = threadIdx.x, ty = threadIdx.y;

    int hw = hw0 + tx;                 // read coalesced along hw
    int c  = c0 + ty;
    if (hw < HW)
        tile[ty][tx] = in[(n * CH + c) * HW + hw];
    __syncthreads();

    int hw2 = hw0 + ty;
    int c2  = c0 + tx;                 // write coalesced along c
    if (hw2 < HW)
        g_ft[(n * HW + hw2) * CH + c2] = tile[tx][ty];
}

// ---- kernel 2: grid (2, K), block 128. lane = channel (cg*128 + t).
__global__ void __launch_bounds__(128) roipool_kernel(
    const float* __restrict__ rois,
    float* __restrict__ out)
{
    __shared__ unsigned s_pos[NBINS];  // hstart<<8 | wstart
    __shared__ unsigned s_cnt[NBINS];  // hc<<8 | wc  (0 if empty)
    __shared__ float    s_out[128 * NBINS];  // 25088 B

    const int k  = blockIdx.y;
    const int cg = blockIdx.x;
    const int t  = threadIdx.x;

    const float* r = rois + k * 5;
    const int b = (int)r[0];

    if (t < NBINS) {
        int x1 = (int)floorf(r[1] * SCALE_F + 0.5f);
        int y1 = (int)floorf(r[2] * SCALE_F + 0.5f);
        int x2 = (int)floorf(r[3] * SCALE_F + 0.5f);
        int y2 = (int)floorf(r[4] * SCALE_F + 0.5f);

        float bin_w = (float)max(x2 - x1 + 1, 1) * (1.0f / POOLED);
        float bin_h = (float)max(y2 - y1 + 1, 1) * (1.0f / POOLED);

        int ph = t / POOLED;
        int pw = t - ph * POOLED;

        int wstart = min(max((int)floorf((float)pw       * bin_w) + x1, 0), FW);
        int wend   = min(max((int)ceilf ((float)(pw + 1) * bin_w) + x1, 0), FW);
        int hstart = min(max((int)floorf((float)ph       * bin_h) + y1, 0), FH);
        int hend   = min(max((int)ceilf ((float)(ph + 1) * bin_h) + y1, 0), FH);

        int hc = hend - hstart;
        int wc = wend - wstart;
        s_cnt[t] = (hc > 0 && wc > 0) ? (unsigned)((hc << 8) | wc) : 0u;
        s_pos[t] = (unsigned)((hstart << 8) | wstart);
    }
    __syncthreads();

    const int c = cg * 128 + t;
    const float* base = g_ft + (size_t)b * (HW * CH) + c;

    for (int bin = 0; bin < NBINS; ++bin) {
        const unsigned cnt = s_cnt[bin];     // uniform across warp (broadcast)
        float m = 0.0f;
        if (cnt) {
            const unsigned pos = s_pos[bin];
            const int hc = (int)(cnt >> 8), wc = (int)(cnt & 0xffu);
            const int hs = (int)(pos >> 8), ws = (int)(pos & 0xffu);
            const float* p0 = base + (hs * FW + ws) * CH;
            m = -FLT_MAX;
            for (int h = 0; h < hc; ++h) {
                const float* p = p0 + h * (FW * CH);
                #pragma unroll 4
                for (int w = 0; w < wc; ++w) {
                    m = fmaxf(m, __ldg(p + w * CH));
                }
            }
        }
        s_out[t * NBINS + bin] = m;          // stride 49 (odd) -> conflict-free
    }
    __syncthreads();

    // coalesced flush: 128 channels * 49 bins, contiguous in out
    float* o = out + (size_t)k * (CH * NBINS) + (size_t)cg * (128 * NBINS);
    #pragma unroll 7
    for (int i = t; i < 128 * NBINS; i += 128)
        o[i] = s_out[i];
}

extern "C" void kernel_launch(void* const* d_in, const int* in_sizes, int n_in,
                              void* d_out, int out_size)
{
    const float* features = (const float*)d_in[0];
    const float* rois     = (const float*)d_in[1];
    float* out            = (float*)d_out;

    const int K = in_sizes[1] / 5;   // 256

    dim3 tg((HW + 31) / 32, CH / 32, NB);   // 79 x 8 x 2
    transpose_kernel<<<tg, dim3(32, 32)>>>(features);

    dim3 rg(2, K);                          // 512 blocks x 128 threads
    roipool_kernel<<<rg, 128>>>(rois, out);
}

// round 4
// speedup vs baseline: 2.5989x; 2.5989x over previous
#include <cuda_runtime.h>
#include <float.h>

// RoIPool (N=2,C=256,H=50,W=50) fp32, rois (K=256,5) -> out (K,256,7,7).
//
// NHWC transpose + lane=channel pooling (uniform windows, zero divergence,
// coalesced 128B loads). R3 failed on occupancy (512 blocks); this round:
// 1024 blocks x 256 threads, warp = (ch-half, bin stride-4), smem-staged
// coalesced output flush.

#define POOLED 7
#define SCALE_F 0.0625f
#define NBINS 49
#define CH 256
#define CPB 64              // channels per block
#define FH 50
#define FW 50
#define HW (FH * FW)        // 2500
#define NB 2

__device__ float g_ft[NB * HW * CH];   // NHWC scratch, 5.12 MB

// ---- kernel 1: NCHW -> NHWC tiled transpose
__global__ void __launch_bounds__(1024) transpose_kernel(const float* __restrict__ in)
{
    __shared__ float tile[32][33];
    const int n   = blockIdx.z;
    const int hw0 = blockIdx.x * 32;
    const int c0  = blockIdx.y * 32;

    int tx = threadIdx.x, ty = threadIdx.y;

    int hw = hw0 + tx;                 // read coalesced along hw
    int c  = c0 + ty;
    if (hw < HW)
        tile[ty][tx] = in[(n * CH + c) * HW + hw];
    __syncthreads();

    int hw2 = hw0 + ty;
    int c2  = c0 + tx;                 // write coalesced along c
    if (hw2 < HW)
        g_ft[(n * HW + hw2) * CH + c2] = tile[tx][ty];
}

// ---- kernel 2: grid (4, K), block 256.
// warp w: ch-half = w&1 (32 channels), bins = (w>>1), +4, +8, ... (<49)
__global__ void __launch_bounds__(256) roipool_kernel(
    const float* __restrict__ rois,
    float* __restrict__ out)
{
    __shared__ unsigned s_pos[NBINS];        // hstart<<8 | wstart
    __shared__ unsigned s_cnt[NBINS];        // hc<<8 | wc (0 if empty)
    __shared__ float    s_out[CPB * NBINS];  // 12544 B

    const int k  = blockIdx.y;
    const int cg = blockIdx.x;
    const int t  = threadIdx.x;
    const int warp = t >> 5;
    const int lane = t & 31;

    const float* r = rois + k * 5;
    const int b = (int)__ldg(r);

    if (t < NBINS) {
        int x1 = (int)floorf(r[1] * SCALE_F + 0.5f);
        int y1 = (int)floorf(r[2] * SCALE_F + 0.5f);
        int x2 = (int)floorf(r[3] * SCALE_F + 0.5f);
        int y2 = (int)floorf(r[4] * SCALE_F + 0.5f);

        float bin_w = (float)max(x2 - x1 + 1, 1) * (1.0f / POOLED);
        float bin_h = (float)max(y2 - y1 + 1, 1) * (1.0f / POOLED);

        int ph = t / POOLED;
        int pw = t - ph * POOLED;

        int wstart = min(max((int)floorf((float)pw       * bin_w) + x1, 0), FW);
        int wend   = min(max((int)ceilf ((float)(pw + 1) * bin_w) + x1, 0), FW);
        int hstart = min(max((int)floorf((float)ph       * bin_h) + y1, 0), FH);
        int hend   = min(max((int)ceilf ((float)(ph + 1) * bin_h) + y1, 0), FH);

        int hc = hend - hstart;
        int wc = wend - wstart;
        s_cnt[t] = (hc > 0 && wc > 0) ? (unsigned)((hc << 8) | wc) : 0u;
        s_pos[t] = (unsigned)((hstart << 8) | wstart);
    }
    __syncthreads();

    const int c_local = (warp & 1) * 32 + lane;      // 0..63
    const int c = cg * CPB + c_local;
    const float* base = g_ft + (size_t)b * (HW * CH) + c;

    for (int bin = (warp >> 1); bin < NBINS; bin += 4) {
        const unsigned cnt = s_cnt[bin];             // uniform across warp
        float m = 0.0f;
        if (cnt) {
            const unsigned pos = s_pos[bin];
            const int hc = (int)(cnt >> 8), wc = (int)(cnt & 0xffu);
            const int hs = (int)(pos >> 8), ws = (int)(pos & 0xffu);
            const float* p0 = base + (hs * FW + ws) * CH;
            m = -FLT_MAX;
            for (int h = 0; h < hc; ++h) {
                const float* p = p0 + h * (FW * CH);
                #pragma unroll 4
                for (int w = 0; w < wc; ++w) {
                    m = fmaxf(m, __ldg(p + w * CH));
                }
            }
        }
        s_out[c_local * NBINS + bin] = m;            // stride 49: conflict-free
    }
    __syncthreads();

    // coalesced flush: 64 channels * 49 bins contiguous in out
    float* o = out + (size_t)k * (CH * NBINS) + (size_t)cg * (CPB * NBINS);
    #pragma unroll
    for (int i = t; i < CPB * NBINS; i += 256)
        o[i] = s_out[i];
}

extern "C" void kernel_launch(void* const* d_in, const int* in_sizes, int n_in,
                              void* d_out, int out_size)
{
    const float* features = (const float*)d_in[0];
    const float* rois     = (const float*)d_in[1];
    float* out            = (float*)d_out;

    const int K = in_sizes[1] / 5;   // 256

    dim3 tg((HW + 31) / 32, CH / 32, NB);   // 79 x 8 x 2
    transpose_kernel<<<tg, dim3(32, 32)>>>(features);

    dim3 rg(CH / CPB, K);                   // 4 x 256 = 1024 blocks
    roipool_kernel<<<rg, 256>>>(rois, out);
}

// round 5
// speedup vs baseline: 4.0314x; 1.5512x over previous
#include <cuda_runtime.h>
#include <float.h>

// RoIPool (N=2,C=256,H=50,W=50) fp32, rois (K=256,5) -> out (K,256,7,7).
//
// NHWC transpose + lane=channel-pair pooling. R4 was latency/instruction
// bound: scalar loads + 12-bin serial chains per warp. Now: float2 LDG.64
// (warp covers all 64 block-channels), bins stride-8 across 8 warps,
// pad-66 [bin][c] smem staging, coalesced flush.

#define POOLED 7
#define SCALE_F 0.0625f
#define NBINS 49
#define CH 256
#define CH2 (CH / 2)        // 128 float2 per cell
#define CPB 64              // channels per block
#define FH 50
#define FW 50
#define HW (FH * FW)        // 2500
#define NB 2
#define SPITCH 66           // smem pitch (floats), even -> 8B-aligned float2

__device__ float g_ft[NB * HW * CH];   // NHWC scratch, 5.12 MB

// ---- kernel 1: NCHW -> NHWC tiled transpose, 4 elems/thread
__global__ void __launch_bounds__(256) transpose_kernel(const float* __restrict__ in)
{
    __shared__ float tile[32][33];
    const int n   = blockIdx.z;
    const int hw0 = blockIdx.x * 32;
    const int c0  = blockIdx.y * 32;

    const int tx = threadIdx.x, ty = threadIdx.y;   // (32, 8)

    const int hw = hw0 + tx;
    if (hw < HW) {
        #pragma unroll
        for (int i = 0; i < 4; ++i) {
            int c = c0 + ty + i * 8;
            tile[ty + i * 8][tx] = in[(n * CH + c) * HW + hw];
        }
    }
    __syncthreads();

    #pragma unroll
    for (int i = 0; i < 4; ++i) {
        int hw2 = hw0 + ty + i * 8;
        if (hw2 < HW)
            g_ft[(n * HW + hw2) * CH + c0 + tx] = tile[tx][ty + i * 8];
    }
}

// ---- kernel 2: grid (4, K), block 256 (8 warps).
// warp w handles bins w, w+8, ..., covering all 64 block-channels via float2.
__global__ void __launch_bounds__(256) roipool_kernel(
    const float* __restrict__ rois,
    float* __restrict__ out)
{
    __shared__ unsigned s_pos[NBINS];          // hstart<<8 | wstart
    __shared__ unsigned s_cnt[NBINS];          // hc<<8 | wc (0 if empty)
    __shared__ float    s_out[NBINS * SPITCH]; // 12.9 KB, [bin][c] padded

    const int k    = blockIdx.y;
    const int cg   = blockIdx.x;
    const int t    = threadIdx.x;
    const int warp = t >> 5;
    const int lane = t & 31;

    const float* r = rois + k * 5;
    const int b = (int)__ldg(r);

    if (t < NBINS) {
        int x1 = (int)floorf(r[1] * SCALE_F + 0.5f);
        int y1 = (int)floorf(r[2] * SCALE_F + 0.5f);
        int x2 = (int)floorf(r[3] * SCALE_F + 0.5f);
        int y2 = (int)floorf(r[4] * SCALE_F + 0.5f);

        float bin_w = (float)max(x2 - x1 + 1, 1) * (1.0f / POOLED);
        float bin_h = (float)max(y2 - y1 + 1, 1) * (1.0f / POOLED);

        int ph = t / POOLED;
        int pw = t - ph * POOLED;

        int wstart = min(max((int)floorf((float)pw       * bin_w) + x1, 0), FW);
        int wend   = min(max((int)ceilf ((float)(pw + 1) * bin_w) + x1, 0), FW);
        int hstart = min(max((int)floorf((float)ph       * bin_h) + y1, 0), FH);
        int hend   = min(max((int)ceilf ((float)(ph + 1) * bin_h) + y1, 0), FH);

        int hc = hend - hstart;
        int wc = wend - wstart;
        s_cnt[t] = (hc > 0 && wc > 0) ? (unsigned)((hc << 8) | wc) : 0u;
        s_pos[t] = (unsigned)((hstart << 8) | wstart);
    }
    __syncthreads();

    // float2 view of NHWC tensor; this thread's channel pair:
    const float2* ft2 = (const float2*)g_ft + (size_t)b * (HW * CH2)
                      + cg * (CPB / 2) + lane;

    for (int bin = warp; bin < NBINS; bin += 8) {
        const unsigned cnt = s_cnt[bin];        // uniform across warp
        float m0 = 0.0f, m1 = 0.0f;
        if (cnt) {
            const unsigned pos = s_pos[bin];
            const int hc = (int)(cnt >> 8), wc = (int)(cnt & 0xffu);
            const int hs = (int)(pos >> 8), ws = (int)(pos & 0xffu);
            const float2* p0 = ft2 + (hs * FW + ws) * CH2;
            m0 = -FLT_MAX; m1 = -FLT_MAX;
            for (int h = 0; h < hc; ++h) {
                const float2* p = p0 + h * (FW * CH2);
                #pragma unroll 4
                for (int w = 0; w < wc; ++w) {
                    float2 v = __ldg(p + w * CH2);
                    m0 = fmaxf(m0, v.x);
                    m1 = fmaxf(m1, v.y);
                }
            }
        }
        *(float2*)&s_out[bin * SPITCH + 2 * lane] = make_float2(m0, m1);
    }
    __syncthreads();

    // coalesced flush: out[k][cg*64 + c][bin], i = c*49 + bin contiguous
    float* o = out + (size_t)k * (CH * NBINS) + (size_t)cg * (CPB * NBINS);
    #pragma unroll
    for (int i = t; i < CPB * NBINS; i += 256) {
        int c   = i / NBINS;
        int bin = i - c * NBINS;
        o[i] = s_out[bin * SPITCH + c];
    }
}

extern "C" void kernel_launch(void* const* d_in, const int* in_sizes, int n_in,
                              void* d_out, int out_size)
{
    const float* features = (const float*)d_in[0];
    const float* rois     = (const float*)d_in[1];
    float* out            = (float*)d_out;

    const int K = in_sizes[1] / 5;   // 256

    dim3 tg((HW + 31) / 32, CH / 32, NB);   // 79 x 8 x 2
    transpose_kernel<<<tg, dim3(32, 8)>>>(features);

    dim3 rg(CH / CPB, K);                   // 4 x 256 = 1024 blocks
    roipool_kernel<<<rg, 256>>>(rois, out);
}